// round 12
// baseline (speedup 1.0000x reference)
#include <cuda_runtime.h>
#include <cstdint>
#include <math.h>

#define NB      4
#define NGRID   512
#define NTARGET 1024
#define NBASIS  5
#define NCH     8

#define NWARP   8                 // warps per CTA = grid chunks
#define CHUNK   (NGRID / NWARP)   // 64 grid points per warp
#define TILES   64                // 16-target tiles per batch
#define TPT     4                 // targets per thread
#define ROW2    (NGRID + 2)       // float2 row stride: 514 -> bank quad 4c, conflict-free
#define STG     (4 * NBASIS * NCH + 8)  // 168 staged h floats per warp

__device__ __forceinline__ float ex2_mufu(float a) {
    float w;
    asm("ex2.approx.ftz.f32 %0, %1;" : "=f"(w) : "f"(a));
    return w;
}

// ---------------------------------------------------------------------------
// Single kernel. CTA = 256 threads = 8 warps, one CTA per (b, 16-target
// tile), grid = 256. Warp w owns grid chunk [w*64, w*64+64); lane = c*4+ts
// covers 8 channels x 4 target slots, TPT=4 -> 16 targets / 8 chains per thread.
//
// Exponent factoring: exp2(-(xs-ts)^2) = exp2(2ts*xs - ts^2) * exp2(-xs^2).
// exp2(-xs^2) is folded into the table h at fill time, so the inner body is
// exactly FMA + MUFU + FMA per exponential and accumulates final values.
// ---------------------------------------------------------------------------
__global__ void __launch_bounds__(256)
finallayer_v12(const float* __restrict__ x_grid,    // [NB][NGRID][NCH]
               const float* __restrict__ h_grid,    // [NB][NGRID][NBASIS][NCH]
               const float* __restrict__ target_x,  // [NB][NTARGET][NCH]
               const float* __restrict__ sigma,     // [NBASIS][NCH]
               const float* __restrict__ g_w,       // [1][NBASIS]
               const float* __restrict__ g_b,       // [1]
               float* __restrict__ out)             // [NB][NTARGET][NCH]
{
    __shared__ __align__(16) float2 tbl[NCH * ROW2];   // (xs, h*exp2(-xs^2)) ~33 KB
    __shared__ float s_stage[NWARP][STG];              // h stage ~5.4 KB
    __shared__ float s_part[NWARP][16 * NCH];          // chunk partials 4 KB
    __shared__ float s_sc[NCH][NBASIS];
    __shared__ int   s_grp[NCH][NBASIS];
    __shared__ int   s_nu[NCH];
    __shared__ float s_gw[NBASIS];

    const int tid  = threadIdx.x;
    const int tile = blockIdx.x & (TILES - 1);
    const int b    = blockIdx.x >> 6;

    // --- per-channel scale dedup (redundant per CTA, trivial) ---
    if (tid < NCH) {
        const float C = 0.8493218002880190f;  // sqrt(0.5 * log2(e))
        float s[NBASIS], uniq[NBASIS];
        int nu = 0;
#pragma unroll
        for (int k = 0; k < NBASIS; ++k)
            s[k] = expf(sigma[k * NCH + tid]) + 1e-6f;
#pragma unroll
        for (int k = 0; k < NBASIS; ++k) {
            int u = -1;
            for (int j = 0; j < nu; ++j)
                if (uniq[j] == s[k]) { u = j; break; }
            if (u < 0) { u = nu; uniq[nu++] = s[k]; }
            s_grp[tid][k] = u;
        }
        s_nu[tid] = nu;
        for (int u = 0; u < nu; ++u) s_sc[tid][u] = C / uniq[u];
    } else if (tid < NCH + NBASIS) {
        s_gw[tid - NCH] = g_w[tid - NCH];
    }
    __syncthreads();

    const int w    = tid >> 5;
    const int lane = tid & 31;

    // --- coalesced fill: warp w owns grid points [w*64, w*64+64) ---
    const float* xg = x_grid + b * (NGRID * NCH);
    const float* hg = h_grid + b * (NGRID * NBASIS * NCH);
    {
        const int cf = lane & 7;              // channel this lane folds
        const int gp = lane >> 3;             // local grid point 0..3
        const float sc0 = s_sc[cf][0];
#pragma unroll
        for (int blk = 0; blk < CHUNK / 4; ++blk) {
            const int g0 = w * CHUNK + blk * 4;           // 4 grid points
            const float* hb = hg + g0 * (NBASIS * NCH);   // 160 contiguous floats
#pragma unroll
            for (int j = 0; j < 5; ++j)                   // coalesced LDG
                s_stage[w][lane + 32 * j] = hb[lane + 32 * j];
            __syncwarp();
            float hv = 0.f;
#pragma unroll
            for (int k = 0; k < NBASIS; ++k)              // conflict-free LDS
                if (s_grp[cf][k] == 0)
                    hv += s_stage[w][gp * (NBASIS * NCH) + k * NCH + cf] * s_gw[k];
            float xs = xg[g0 * NCH + lane] * sc0;         // coalesced
            tbl[cf * ROW2 + g0 + gp] =
                make_float2(xs, hv * ex2_mufu(-xs * xs)); // fold exp2(-xs^2) into h
            __syncwarp();
        }
    }
    __syncthreads();

    // --- main loop: lane = c*4 + tslot; targets tslot + 4j ---
    const int c     = lane >> 2;
    const int tslot = lane & 3;
    const float sc0 = s_sc[c][0];

    float p2t[TPT], nt2[TPT], acc[TPT];
#pragma unroll
    for (int j = 0; j < TPT; ++j) {
        int t = tile * 16 + tslot + 4 * j;
        float ts = __ldg(&target_x[(b * NTARGET + t) * NCH + c]) * sc0;
        p2t[j] = ts + ts;                     // 2*ts
        nt2[j] = -ts * ts;                    // -ts^2
        acc[j] = 0.f;
    }

    const float4* pc = (const float4*)(tbl + c * ROW2) + w * (CHUNK / 2);
#pragma unroll 8
    for (int gg = 0; gg < CHUNK / 2; ++gg) {
        float4 q = pc[gg];                    // (xs0, h0', xs1, h1') broadcast LDS
#pragma unroll
        for (int j = 0; j < TPT; ++j) {
            float a0 = fmaf(q.x, p2t[j], nt2[j]);
            float a1 = fmaf(q.z, p2t[j], nt2[j]);
            acc[j] = fmaf(ex2_mufu(a0), q.y, acc[j]);
            acc[j] = fmaf(ex2_mufu(a1), q.w, acc[j]);
        }
    }

    // --- generic cold path: extra unique scales (not taken for uniform sigma) ---
    const int nu  = s_nu[c];
    const int gc0 = w * CHUNK;
    for (int u = 1; u < nu; ++u) {
        const float sc = s_sc[c][u];
        for (int g = 0; g < CHUNK; ++g) {
            float xv = __ldg(&xg[(gc0 + g) * NCH + c]);
            float hv = 0.f;
#pragma unroll
            for (int k = 0; k < NBASIS; ++k)
                if (s_grp[c][k] == u)
                    hv += __ldg(&hg[((gc0 + g) * NBASIS + k) * NCH + c]) * s_gw[k];
            float xs = xv * sc;
#pragma unroll
            for (int j = 0; j < TPT; ++j) {
                int t = tile * 16 + tslot + 4 * j;
                float ts = __ldg(&target_x[(b * NTARGET + t) * NCH + c]) * sc;
                float d  = xs - ts;
                acc[j] = fmaf(ex2_mufu(-d * d), hv, acc[j]);
            }
        }
    }

    // --- stash partials, intra-CTA reduction over the 8 chunks ---
#pragma unroll
    for (int j = 0; j < TPT; ++j)
        s_part[w][(tslot + 4 * j) * NCH + c] = acc[j];
    __syncthreads();

    if (tid < 16 * NCH) {                     // tid = t_local*8 + c
        float sum = __ldg(g_b);
#pragma unroll
        for (int s = 0; s < NWARP; ++s)       // fixed order -> deterministic
            sum += s_part[s][tid];
        out[(b * NTARGET + tile * 16) * NCH + tid] = sum;  // coalesced
    }
}

// ---------------------------------------------------------------------------
extern "C" void kernel_launch(void* const* d_in, const int* in_sizes, int n_in,
                              void* d_out, int out_size) {
    const float* x_grid   = (const float*)d_in[0];  // [4,512,8]
    const float* h_grid   = (const float*)d_in[1];  // [4,512,5,8]
    const float* target_x = (const float*)d_in[2];  // [4,1024,8]
    const float* sigma    = (const float*)d_in[3];  // [5,8]
    const float* g_w      = (const float*)d_in[4];  // [1,5]
    const float* g_b      = (const float*)d_in[5];  // [1]
    float* out = (float*)d_out;                     // [4,1024,8]

    finallayer_v12<<<NB * TILES, 256>>>(
        x_grid, h_grid, target_x, sigma, g_w, g_b, out);
}

// round 14
// speedup vs baseline: 1.0151x; 1.0151x over previous
#include <cuda_runtime.h>
#include <cstdint>
#include <math.h>

#define NB      4
#define NGRID   512
#define NTARGET 1024
#define NBASIS  5
#define NCH     8

#define NCHUNK  16                // grid chunks per CTA (32 pts each)
#define CHUNK   (NGRID / NCHUNK)  // 32
#define TILES   64                // 16-target tiles per batch
#define ROW2    (NGRID + 2)       // float2 row stride 514 -> conflict-free banks

__device__ __forceinline__ float ex2_mufu(float a) {
    float w;
    asm("ex2.approx.ftz.f32 %0, %1;" : "=f"(w) : "f"(a));
    return w;
}
// FMA-pipe exp2 for a <= 0 (rel err ~3e-5). 8 fma-pipe + 2 alu ops.
__device__ __forceinline__ float ex2_poly(float a) {
    a = fmaxf(a, -126.0f);
    float r = a + 12582912.0f;            // 1.5*2^23 round-to-int trick
    float n = r - 12582912.0f;
    float f = a - n;                      // f in [-0.5, 0.5]
    float p = 0.0096181291f;
    p = fmaf(p, f, 0.0555041087f);
    p = fmaf(p, f, 0.2402265070f);
    p = fmaf(p, f, 0.6931471806f);
    p = fmaf(p, f, 1.0f);
    int ib = __float_as_int(r) << 23;     // == n << 23 (low bits of magic shift out)
    return __int_as_float(__float_as_int(p) + ib);
}

// ---------------------------------------------------------------------------
// Single kernel, R8's proven shape: 256 CTAs x 1024 threads (occ ~78%).
// CTA = (b, 16-target tile). Warp w: chunk = w>>1 (32 grid pts), tg = w&1
// (targets tg*8..tg*8+7). Lane: c = lane>>2, tslot = lane&3; TPT=2 ->
// t_local = tg*8 + tslot + 4j, j=0,1. Thread = 32 grid x 2 targets = 64 exps.
//
// Math: exp2(-(xs-ts)^2) = exp2(2ts*xs - ts^2) * 2^(-xs^2); the 2^(-xs^2)
// factor is folded into the table h. Inner body = FMA + EXP + FMA.
// Hybrid: per 8-exp group, 3 go through the FMA-pipe poly, 5 through MUFU,
// balancing the two pipes (MUFU ex2 measured rt ~16/SMSP).
// ---------------------------------------------------------------------------
__global__ void __launch_bounds__(1024)
finallayer_v13(const float* __restrict__ x_grid,    // [NB][NGRID][NCH]
               const float* __restrict__ h_grid,    // [NB][NGRID][NBASIS][NCH]
               const float* __restrict__ target_x,  // [NB][NTARGET][NCH]
               const float* __restrict__ sigma,     // [NBASIS][NCH]
               const float* __restrict__ g_w,       // [1][NBASIS]
               const float* __restrict__ g_b,       // [1]
               float* __restrict__ out)             // [NB][NTARGET][NCH]
{
    __shared__ __align__(16) float2 tbl[NCH * ROW2];   // (xs, h*2^-xs^2) ~33 KB
    __shared__ float s_part[NCHUNK][16 * NCH];         // chunk partials 8 KB
    __shared__ float s_sc[NCH][NBASIS];
    __shared__ int   s_grp[NCH][NBASIS];
    __shared__ int   s_nu[NCH];
    __shared__ float s_gw[NBASIS];

    const int tid  = threadIdx.x;
    const int tile = blockIdx.x & (TILES - 1);
    const int b    = blockIdx.x >> 6;

    // --- per-channel scale dedup (redundant per CTA, trivial) ---
    if (tid < NCH) {
        const float C = 0.8493218002880190f;  // sqrt(0.5 * log2(e))
        float s[NBASIS], uniq[NBASIS];
        int nu = 0;
#pragma unroll
        for (int k = 0; k < NBASIS; ++k)
            s[k] = expf(sigma[k * NCH + tid]) + 1e-6f;
#pragma unroll
        for (int k = 0; k < NBASIS; ++k) {
            int u = -1;
            for (int j = 0; j < nu; ++j)
                if (uniq[j] == s[k]) { u = j; break; }
            if (u < 0) { u = nu; uniq[nu++] = s[k]; }
            s_grp[tid][k] = u;
        }
        s_nu[tid] = nu;
        for (int u = 0; u < nu; ++u) s_sc[tid][u] = C / uniq[u];
    } else if (tid < NCH + NBASIS) {
        s_gw[tid - NCH] = g_w[tid - NCH];
    }
    __syncthreads();

    // --- fill table (style proven perf-neutral in R8 vs R9) ---
    const float* xg = x_grid + b * (NGRID * NCH);
    const float* hg = h_grid + b * (NGRID * NBASIS * NCH);
    for (int i = tid; i < NGRID * NCH; i += 1024) {
        const int c = i & 7, g = i >> 3;
        float hv = 0.f;
#pragma unroll
        for (int k = 0; k < NBASIS; ++k)
            if (s_grp[c][k] == 0)
                hv += __ldg(&hg[(g * NBASIS + k) * NCH + c]) * s_gw[k];
        float xs = xg[i] * s_sc[c][0];
        tbl[c * ROW2 + g] = make_float2(xs, hv * ex2_mufu(-xs * xs));
    }
    __syncthreads();

    // --- main loop ---
    const int w     = tid >> 5;
    const int lane  = tid & 31;
    const int chunk = w >> 1;
    const int tg    = w & 1;
    const int c     = lane >> 2;
    const int tslot = lane & 3;
    const float sc0 = s_sc[c][0];

    float p2t[2], nt2[2], acc[2];
#pragma unroll
    for (int j = 0; j < 2; ++j) {
        int t = tile * 16 + tg * 8 + tslot + 4 * j;
        float ts = __ldg(&target_x[(b * NTARGET + t) * NCH + c]) * sc0;
        p2t[j] = ts + ts;
        nt2[j] = -ts * ts;
        acc[j] = 0.f;
    }

    // 32 grid pts = 16 float4; process 2 float4 per step -> 8 exps/step.
    const float4* pc = (const float4*)(tbl + c * ROW2) + chunk * (CHUNK / 2);
#pragma unroll
    for (int gg = 0; gg < CHUNK / 2; gg += 2) {
        float4 q0 = pc[gg];
        float4 q1 = pc[gg + 1];
        // exponents: a[q][pt][j]
        float a00 = fmaf(q0.x, p2t[0], nt2[0]);
        float a01 = fmaf(q0.x, p2t[1], nt2[1]);
        float a10 = fmaf(q0.z, p2t[0], nt2[0]);
        float a11 = fmaf(q0.z, p2t[1], nt2[1]);
        float b00 = fmaf(q1.x, p2t[0], nt2[0]);
        float b01 = fmaf(q1.x, p2t[1], nt2[1]);
        float b10 = fmaf(q1.z, p2t[0], nt2[0]);
        float b11 = fmaf(q1.z, p2t[1], nt2[1]);
        // 3 poly (FMA pipe) + 5 MUFU
        acc[0] = fmaf(ex2_poly(a00), q0.y, acc[0]);
        acc[1] = fmaf(ex2_poly(a01), q0.y, acc[1]);
        acc[0] = fmaf(ex2_poly(a10), q0.w, acc[0]);
        acc[1] = fmaf(ex2_mufu(a11), q0.w, acc[1]);
        acc[0] = fmaf(ex2_mufu(b00), q1.y, acc[0]);
        acc[1] = fmaf(ex2_mufu(b01), q1.y, acc[1]);
        acc[0] = fmaf(ex2_mufu(b10), q1.w, acc[0]);
        acc[1] = fmaf(ex2_mufu(b11), q1.w, acc[1]);
    }

    // --- generic cold path: extra unique scales (not taken for uniform sigma) ---
    const int nu  = s_nu[c];
    const int gc0 = chunk * CHUNK;
    for (int u = 1; u < nu; ++u) {
        const float sc = s_sc[c][u];
        for (int g = 0; g < CHUNK; ++g) {
            float xv = __ldg(&xg[(gc0 + g) * NCH + c]);
            float hv = 0.f;
#pragma unroll
            for (int k = 0; k < NBASIS; ++k)
                if (s_grp[c][k] == u)
                    hv += __ldg(&hg[((gc0 + g) * NBASIS + k) * NCH + c]) * s_gw[k];
            float xs = xv * sc;
#pragma unroll
            for (int j = 0; j < 2; ++j) {
                int t = tile * 16 + tg * 8 + tslot + 4 * j;
                float ts = __ldg(&target_x[(b * NTARGET + t) * NCH + c]) * sc;
                float d  = xs - ts;
                acc[j] = fmaf(ex2_mufu(-d * d), hv, acc[j]);
            }
        }
    }

    // --- stash partials, intra-CTA reduction over the 16 chunks ---
#pragma unroll
    for (int j = 0; j < 2; ++j)
        s_part[chunk][(tg * 8 + tslot + 4 * j) * NCH + c] = acc[j];
    __syncthreads();

    if (tid < 16 * NCH) {                 // tid = t_local*8 + c
        float sum = __ldg(g_b);
#pragma unroll
        for (int s = 0; s < NCHUNK; ++s)  // fixed order -> deterministic
            sum += s_part[s][tid];
        out[(b * NTARGET + tile * 16) * NCH + tid] = sum;  // coalesced
    }
}

// ---------------------------------------------------------------------------
extern "C" void kernel_launch(void* const* d_in, const int* in_sizes, int n_in,
                              void* d_out, int out_size) {
    const float* x_grid   = (const float*)d_in[0];  // [4,512,8]
    const float* h_grid   = (const float*)d_in[1];  // [4,512,5,8]
    const float* target_x = (const float*)d_in[2];  // [4,1024,8]
    const float* sigma    = (const float*)d_in[3];  // [5,8]
    const float* g_w      = (const float*)d_in[4];  // [1,5]
    const float* g_b      = (const float*)d_in[5];  // [1]
    float* out = (float*)d_out;                     // [4,1024,8]

    finallayer_v13<<<NB * TILES, 1024>>>(
        x_grid, h_grid, target_x, sigma, g_w, g_b, out);
}

// round 15
// speedup vs baseline: 1.3663x; 1.3459x over previous
#include <cuda_runtime.h>
#include <cstdint>
#include <math.h>

#define NB      4
#define NGRID   512
#define NTARGET 1024
#define NBASIS  5
#define NCH     8

#define SPLIT   16                // grid chunks (one per CTA group)
#define CHUNK   (NGRID / SPLIT)   // 32 grid points per CTA
#define TILES   16                // 64-target tiles per batch
#define TPT     4                 // targets per thread
#define ROW2    (CHUNK + 2)       // float2 row stride (34) -> 16B-aligned rows

// Partial sums: [SPLIT][NB][NTARGET][NCH] = 2 MB, L2-resident
__device__ float d_part[SPLIT * NB * NTARGET * NCH];

__device__ __forceinline__ float ex2_mufu(float a) {
    float w;
    asm("ex2.approx.ftz.f32 %0, %1;" : "=f"(w) : "f"(a));
    return w;
}

// ---------------------------------------------------------------------------
// Main kernel: 1024 CTAs x 128 threads (the R3 small-CTA shape that measured
// fastest, at 2x the CTA count for wave balance). CTA = (b, 64-target tile,
// 32-pt grid chunk). Warp = 2 channels x 16 target-lanes, TPT=4.
// Math: exp2(-(xs-ts)^2) = exp2(2ts*xs - ts^2) * 2^(-xs^2), the last factor
// folded into the table h -> inner body is FMA + MUFU + FMA per exponential.
// ---------------------------------------------------------------------------
__global__ void __launch_bounds__(128)
finallayer_part(const float* __restrict__ x_grid,    // [NB][NGRID][NCH]
                const float* __restrict__ h_grid,    // [NB][NGRID][NBASIS][NCH]
                const float* __restrict__ target_x,  // [NB][NTARGET][NCH]
                const float* __restrict__ sigma,     // [NBASIS][NCH]
                const float* __restrict__ g_w)       // [1][NBASIS]
{
    __shared__ __align__(16) float2 tbl[NCH * ROW2];  // (xs, h*2^-xs^2) ~2.2 KB
    __shared__ float s_part[64 * NCH];                // tile partials, 2 KB
    __shared__ float s_sc[NCH][NBASIS];
    __shared__ int   s_grp[NCH][NBASIS];
    __shared__ int   s_nu[NCH];
    __shared__ float s_gw[NBASIS];

    const int tid   = threadIdx.x;
    const int chunk = blockIdx.x & (SPLIT - 1);
    const int tile  = (blockIdx.x >> 4) & (TILES - 1);
    const int b     = blockIdx.x >> 8;          // bx = b*256 + tile*16 + chunk
    const int g0    = chunk * CHUNK;

    // --- per-channel scale dedup (redundant per CTA, trivial) ---
    if (tid < NCH) {
        const float C = 0.8493218002880190f;    // sqrt(0.5 * log2(e))
        float s[NBASIS], uniq[NBASIS];
        int nu = 0;
#pragma unroll
        for (int k = 0; k < NBASIS; ++k)
            s[k] = expf(sigma[k * NCH + tid]) + 1e-6f;
#pragma unroll
        for (int k = 0; k < NBASIS; ++k) {
            int u = -1;
            for (int j = 0; j < nu; ++j)
                if (uniq[j] == s[k]) { u = j; break; }
            if (u < 0) { u = nu; uniq[nu++] = s[k]; }
            s_grp[tid][k] = u;
        }
        s_nu[tid] = nu;
        for (int u = 0; u < nu; ++u) s_sc[tid][u] = C / uniq[u];
    } else if (tid < NCH + NBASIS) {
        s_gw[tid - NCH] = g_w[tid - NCH];
    }
    __syncthreads();

    // --- fill the 32-pt x 8-ch table (2 entries per thread) ---
    const float* xg = x_grid + (b * NGRID + g0) * NCH;
    const float* hg = h_grid + (b * NGRID + g0) * NBASIS * NCH;
    for (int i = tid; i < CHUNK * NCH; i += 128) {
        const int c = i & 7, g = i >> 3;
        float hv = 0.f;
#pragma unroll
        for (int k = 0; k < NBASIS; ++k)
            if (s_grp[c][k] == 0)
                hv += hg[(g * NBASIS + k) * NCH + c] * s_gw[k];
        float xs = xg[i] * s_sc[c][0];
        tbl[c * ROW2 + g] = make_float2(xs, hv * ex2_mufu(-xs * xs));
    }
    __syncthreads();

    // --- main loop: warp = 2 channels, lane 0-15 -> c0, 16-31 -> c1; TPT=4 ---
    const int lane = tid & 31;
    const int c    = ((tid >> 5) << 1) | (lane >> 4);
    const int tl   = lane & 15;                 // local target base
    const float sc0 = s_sc[c][0];

    float p2t[TPT], nt2[TPT], acc[TPT];
#pragma unroll
    for (int j = 0; j < TPT; ++j) {
        int t = tile * 64 + tl + 16 * j;
        float ts = __ldg(&target_x[(b * NTARGET + t) * NCH + c]) * sc0;
        p2t[j] = ts + ts;                       // 2*ts
        nt2[j] = -ts * ts;                      // -ts^2
        acc[j] = 0.f;
    }

    const float4* pc = (const float4*)(tbl + c * ROW2);  // broadcast LDS.128
#pragma unroll
    for (int gg = 0; gg < CHUNK / 2; ++gg) {
        float4 q = pc[gg];                      // (xs0, h0', xs1, h1')
#pragma unroll
        for (int j = 0; j < TPT; ++j) {
            float a0 = fmaf(q.x, p2t[j], nt2[j]);
            float a1 = fmaf(q.z, p2t[j], nt2[j]);
            acc[j] = fmaf(ex2_mufu(a0), q.y, acc[j]);
            acc[j] = fmaf(ex2_mufu(a1), q.w, acc[j]);
        }
    }

    // --- generic cold path: extra unique scales (not taken for uniform sigma) ---
    const int nu = s_nu[c];
    for (int u = 1; u < nu; ++u) {
        const float sc = s_sc[c][u];
        for (int g = 0; g < CHUNK; ++g) {
            float xv = __ldg(&xg[g * NCH + c]);
            float hv = 0.f;
#pragma unroll
            for (int k = 0; k < NBASIS; ++k)
                if (s_grp[c][k] == u)
                    hv += __ldg(&hg[(g * NBASIS + k) * NCH + c]) * s_gw[k];
            float xs = xv * sc;
#pragma unroll
            for (int j = 0; j < TPT; ++j) {
                int t = tile * 64 + tl + 16 * j;
                float ts = __ldg(&target_x[(b * NTARGET + t) * NCH + c]) * sc;
                float d  = xs - ts;
                acc[j] = fmaf(ex2_mufu(-d * d), hv, acc[j]);
            }
        }
    }

    // --- stage partials in smem, then fully-coalesced float4 store ---
#pragma unroll
    for (int j = 0; j < TPT; ++j)
        s_part[(tl + 16 * j) * NCH + c] = acc[j];
    __syncthreads();

    float4* dst = (float4*)(d_part +
        ((size_t)(chunk * NB + b) * NTARGET + tile * 64) * NCH);
    dst[tid] = ((const float4*)s_part)[tid];    // 512 floats = 128 float4
}

// ---------------------------------------------------------------------------
// Reduce (PDL secondary): waits for the main grid, then sums SPLIT partials.
// Launch latency overlaps the main kernel via programmatic stream serialization.
// ---------------------------------------------------------------------------
__global__ void __launch_bounds__(256)
finallayer_red(const float* __restrict__ g_b, float* __restrict__ out)
{
    cudaGridDependencySynchronize();            // wait for main grid completion
    const int i = blockIdx.x * 256 + threadIdx.x;   // 0 .. 32767
    float acc = __ldg(g_b);
#pragma unroll
    for (int s = 0; s < SPLIT; ++s)             // fixed order -> deterministic
        acc += d_part[s * (NB * NTARGET * NCH) + i];
    out[i] = acc;
}

// ---------------------------------------------------------------------------
extern "C" void kernel_launch(void* const* d_in, const int* in_sizes, int n_in,
                              void* d_out, int out_size) {
    const float* x_grid   = (const float*)d_in[0];  // [4,512,8]
    const float* h_grid   = (const float*)d_in[1];  // [4,512,5,8]
    const float* target_x = (const float*)d_in[2];  // [4,1024,8]
    const float* sigma    = (const float*)d_in[3];  // [5,8]
    const float* g_w      = (const float*)d_in[4];  // [1,5]
    const float* g_b      = (const float*)d_in[5];  // [1]
    float* out = (float*)d_out;                     // [4,1024,8]

    finallayer_part<<<NB * TILES * SPLIT, 128>>>(
        x_grid, h_grid, target_x, sigma, g_w);

    cudaLaunchConfig_t cfg = {};
    cfg.gridDim  = dim3((NB * NTARGET * NCH) / 256);  // 128 blocks
    cfg.blockDim = dim3(256);
    cudaLaunchAttribute attr[1];
    attr[0].id = cudaLaunchAttributeProgrammaticStreamSerialization;
    attr[0].val.programmaticStreamSerializationAllowed = 1;
    cfg.attrs = attr;
    cfg.numAttrs = 1;
    cudaLaunchKernelEx(&cfg, finallayer_red, g_b, out);
}